// round 10
// baseline (speedup 1.0000x reference)
#include <cuda_runtime.h>
#include <cuda_bf16.h>
#include <cstdint>

#define BINS  10
#define WPB   4                 // warps per block
#define NTHR  128
#define GRID_BLKS 888           // 148 SMs * 6 blocks

__device__ float    g_cnt[BINS];
__device__ float    g_sum[BINS];
__device__ unsigned g_work = 0;   // dynamic tile ticket
__device__ unsigned g_done = 0;   // both reset by last block (graph-replay safe)

// GHM-C loss, thread-per-row with REGISTER exp + smem partial-sum transpose.
// Load phase (per 32-row tile, per warp): 16 coalesced LDG.128 (each covers
// 2 rows x 16 cols... lane k holds cols 4*(k&15)..+3 of row 2p+(k>>4)); exp
// applied in registers immediately; each lane stores ONE partial sum per pair
// to smem[row][c4] ([row][17] layout, conflict-free). 2.2KB smem/tile (vs
// 16KB for a full transpose), no cp.async, no wait_group.
// Compute phase: lane=row sums its 16 partials (LDS.32, conflict-free);
// x[row][t] gathered straight from gmem (L2-resident: streamed <1us ago).
// Tiles distributed via global atomic ticket, prefetched one tile ahead.
__global__ __launch_bounds__(NTHR, 6)
void ghm_fused(const float4* __restrict__ x4,
               const float*  __restrict__ x,
               const int*    __restrict__ target,
               const float*  __restrict__ weight,
               const int*    __restrict__ stage,
               float*        __restrict__ out,
               int nrows, float invN)
{
    __shared__ float part[WPB][32 * 17];
    __shared__ float s_cnt[BINS];
    __shared__ float s_sum[BINS];
    __shared__ bool  s_last;

    const int tid  = threadIdx.x;
    const int wi   = tid >> 5;
    const int lane = tid & 31;
    const int half = lane >> 4;
    const int c4   = lane & 15;

    if (tid < BINS) { s_cnt[tid] = 0.0f; s_sum[tid] = 0.0f; }

    const int sraw = __ldg(stage);
    const bool stage1 = (sraw == 1) || (__int_as_float(sraw) == 1.0f);

    const int ntiles = (nrows + 31) >> 5;
    float* pw = part[wi];

    float csum[BINS];
    #pragma unroll
    for (int b = 0; b < BINS; b++) csum[b] = 0.0f;
    unsigned long long cA = 0, cB = 0;   // packed counts: 12 bits/bin, 5 bins each

    // first ticket
    unsigned my = 0;
    if (lane == 0) my = atomicAdd(&g_work, 1u);
    my = __shfl_sync(0xffffffffu, my, 0);

    while (my < (unsigned)ntiles) {
        unsigned nxt_raw = 0;
        if (lane == 0) nxt_raw = atomicAdd(&g_work, 1u);   // latency hidden by tile

        const int rb   = (int)my << 5;
        const int rowL = min(rb + lane, nrows - 1);
        const int t    = __ldg(target + rowL);              // coalesced, early

        float xt;
        if (rb + 32 <= nrows) {
            // hot path: full tile, unguarded addresses
            const float4* bp = x4 + ((size_t)(rb + half)) * 16 + c4;
            float4 v0[4], v1[4];
            #pragma unroll
            for (int j = 0; j < 4; j++) v0[j] = __ldcs(bp + 32 * j);        // pairs 0-3
            #pragma unroll
            for (int j = 0; j < 4; j++) v1[j] = __ldcs(bp + 32 * (4 + j)); // pairs 4-7
            // process pairs 0-3
            #pragma unroll
            for (int j = 0; j < 4; j++) {
                const float e = (__expf(v0[j].x) + __expf(v0[j].y))
                              + (__expf(v0[j].z) + __expf(v0[j].w));
                pw[(2 * j + half) * 17 + c4] = e;
            }
            #pragma unroll
            for (int j = 0; j < 4; j++) v0[j] = __ldcs(bp + 32 * (8 + j)); // pairs 8-11
            // process pairs 4-7
            #pragma unroll
            for (int j = 0; j < 4; j++) {
                const float e = (__expf(v1[j].x) + __expf(v1[j].y))
                              + (__expf(v1[j].z) + __expf(v1[j].w));
                pw[(2 * (4 + j) + half) * 17 + c4] = e;
            }
            #pragma unroll
            for (int j = 0; j < 4; j++) v1[j] = __ldcs(bp + 32 * (12 + j)); // pairs 12-15
            // x[row][t] gather — t long since arrived; L2-resident row data
            xt = __ldg(x + (size_t)rowL * 64 + t);
            // process pairs 8-11
            #pragma unroll
            for (int j = 0; j < 4; j++) {
                const float e = (__expf(v0[j].x) + __expf(v0[j].y))
                              + (__expf(v0[j].z) + __expf(v0[j].w));
                pw[(2 * (8 + j) + half) * 17 + c4] = e;
            }
            // process pairs 12-15
            #pragma unroll
            for (int j = 0; j < 4; j++) {
                const float e = (__expf(v1[j].x) + __expf(v1[j].y))
                              + (__expf(v1[j].z) + __expf(v1[j].w));
                pw[(2 * (12 + j) + half) * 17 + c4] = e;
            }
        } else {
            // tail tile: clamped rows (duplicates harmless; hist is guarded)
            #pragma unroll
            for (int p = 0; p < 16; p++) {
                const int r = min(rb + 2 * p + half, nrows - 1);
                const float4 v = __ldcs(x4 + (size_t)r * 16 + c4);
                const float e = (__expf(v.x) + __expf(v.y))
                              + (__expf(v.z) + __expf(v.w));
                pw[(2 * p + half) * 17 + c4] = e;
            }
            xt = __ldg(x + (size_t)rowL * 64 + t);
        }
        __syncwarp();

        // ---- compute phase: lane = row rb+lane ----
        {
            float a0 = 0.f, a1 = 0.f, a2 = 0.f, a3 = 0.f;
            const float* rp = pw + lane * 17;
            #pragma unroll
            for (int c = 0; c < 4; c++) {
                a0 += rp[c];      a1 += rp[4 + c];
                a2 += rp[8 + c];  a3 += rp[12 + c];
            }
            const float s = (a0 + a1) + (a2 + a3);

            const float log_pt = xt - __logf(s);
            const float wt = stage1 ? 1.0f : __ldg(weight + t);
            const float ce = -wt * log_pt;
            const float g  = fabsf(__expf(log_pt) - 1.0f);
            int b = (int)(g * 9.9999f);          // floor(g*(BINS-1e-4)), g>=0
            b = min(b, BINS - 1);

            if (rb + lane < nrows) {
                if (b < 5) cA += 1ull << (b * 12);
                else       cB += 1ull << ((b - 5) * 12);
                #pragma unroll
                for (int k = 0; k < BINS; k++)
                    csum[k] += (b == k) ? ce : 0.0f;
            }
        }
        __syncwarp();            // before next tile overwrites partials

        my = __shfl_sync(0xffffffffu, nxt_raw, 0);
    }

    // unpack counts; fold 20 accumulators across the warp (once)
    float cnt[BINS];
    #pragma unroll
    for (int k = 0; k < 5; k++) {
        cnt[k]     = (float)((cA >> (k * 12)) & 0xFFFull);
        cnt[k + 5] = (float)((cB >> (k * 12)) & 0xFFFull);
    }
    #pragma unroll
    for (int k = 0; k < BINS; k++) {
        #pragma unroll
        for (int m = 16; m > 0; m >>= 1) {
            cnt[k]  += __shfl_xor_sync(0xffffffffu, cnt[k],  m);
            csum[k] += __shfl_xor_sync(0xffffffffu, csum[k], m);
        }
    }
    __syncthreads();                 // s_cnt/s_sum zero-init visible
    if (lane == 0) {
        #pragma unroll
        for (int k = 0; k < BINS; k++) {
            atomicAdd(&s_cnt[k], cnt[k]);
            atomicAdd(&s_sum[k], csum[k]);
        }
    }
    __syncthreads();
    if (tid < BINS) {
        atomicAdd(&g_cnt[tid], s_cnt[tid]);
        atomicAdd(&g_sum[tid], s_sum[tid]);
    }
    __threadfence();
    __syncthreads();
    if (tid == 0) {
        const unsigned prev = atomicAdd(&g_done, 1u);
        s_last = (prev == gridDim.x - 1);
    }
    __syncthreads();

    if (s_last && tid == 0) {
        float c[BINS], su[BINS];
        #pragma unroll
        for (int b = 0; b < BINS; b++) { c[b] = g_cnt[b]; su[b] = g_sum[b]; }
        float nonempty = 0.0f;
        #pragma unroll
        for (int b = 0; b < BINS; b++)
            nonempty += (c[b] > 0.0f) ? 1.0f : 0.0f;
        float loss = 0.0f;
        #pragma unroll
        for (int b = 0; b < BINS; b++)
            loss += su[b] / fmaxf(c[b] * nonempty, 0.0001f);
        out[0] = loss * invN;
        // self-clean for next graph replay
        #pragma unroll
        for (int b = 0; b < BINS; b++) { g_cnt[b] = 0.0f; g_sum[b] = 0.0f; }
        g_work = 0;
        g_done = 0;
        __threadfence();
    }
}

extern "C" void kernel_launch(void* const* d_in, const int* in_sizes, int n_in,
                              void* d_out, int out_size) {
    const float* x      = (const float*)d_in[0];
    const int*   target = (const int*)  d_in[1];
    const float* weight = (const float*)d_in[2];
    const int*   stage  = (const int*)  d_in[3];
    float*       out    = (float*)      d_out;

    const int N = in_sizes[1];   // number of samples

    ghm_fused<<<GRID_BLKS, NTHR>>>((const float4*)x, x, target, weight, stage,
                                   out, N, 1.0f / (float)N);
}

// round 11
// speedup vs baseline: 1.0380x; 1.0380x over previous
#include <cuda_runtime.h>
#include <cuda_bf16.h>
#include <cstdint>

#define BINS  10
#define WPB   7                 // warps per block
#define NTHR  224
#define GRID_BLKS 296           // 148 SMs * 2 blocks (smem-limited)
// per-warp buffer: 32 rows x 64 f32 = 8 KB, XOR-swizzled (no padding):
//   physical 16B-chunk of (row, c) = row*16 + (c ^ (row & 7))
// STS (cp.async) and LDS.128 row sweeps are both bank-conflict-free.
// NEW vs R8: dependency-free prefetch.global.L2 stream ~2 iterations ahead
// of the cp.async restage -> restage hits L2 (~234cyc) instead of DRAM
// (~577cyc); DRAM demand is driven by the unconstrained prefetch stream.

__device__ float    g_cnt[BINS];
__device__ float    g_sum[BINS];
__device__ unsigned g_done = 0;   // last block resets everything (graph-replay safe)

__device__ __forceinline__ void cp_async16(unsigned dst, const void* src) {
    asm volatile("cp.async.cg.shared.global [%0], [%1], 16;\n" :: "r"(dst), "l"(src));
}
__device__ __forceinline__ void cp_commit() {
    asm volatile("cp.async.commit_group;\n");
}
template <int N>
__device__ __forceinline__ void cp_wait() {
    asm volatile("cp.async.wait_group %0;\n" :: "n"(N));
}
__device__ __forceinline__ void prefetch_l2(const void* p) {
    asm volatile("prefetch.global.L2 [%0];" :: "l"(p));
}

__global__ __launch_bounds__(NTHR, 2)
void ghm_fused(const float* __restrict__ x,
               const int*   __restrict__ target,
               const float* __restrict__ weight,
               const int*   __restrict__ stage,
               float*       __restrict__ out,
               int nrows, float invN)
{
    __shared__ __align__(16) float tile[WPB][2][32 * 64];   // 8 KB per buffer
    __shared__ float s_cnt[BINS];
    __shared__ float s_sum[BINS];
    __shared__ bool  s_last;

    const int tid  = threadIdx.x;
    const int wi   = tid >> 5;
    const int lane = tid & 31;

    if (tid < BINS) { s_cnt[tid] = 0.0f; s_sum[tid] = 0.0f; }

    const int sraw = __ldg(stage);
    const bool stage1 = (sraw == 1) || (__int_as_float(sraw) == 1.0f);

    const int gw     = blockIdx.x * WPB + wi;   // global warp id
    const int nw     = gridDim.x * WPB;         // total warps
    const int ntiles = (nrows + 31) >> 5;
    const long long nfloats = (long long)nrows * 64;

    // staging map: lane k copies chunk (row 2j+(k>>4), cols 4*(k&15)..+3)
    const int r2 = lane >> 4;
    const int c4 = lane & 15;

    unsigned dstS[2];
    #pragma unroll
    for (int s = 0; s < 2; s++)
        dstS[s] = (unsigned)__cvta_generic_to_shared(&tile[wi][s][0]);
    const float* srcb = x + (size_t)r2 * 64 + c4 * 4;

    // prefetch one full 8KB tile: 64 lines of 128B, 2 per lane (clamped)
    auto l2_prefetch_tile = [&](int tt) {
        if (tt < ntiles) {
            const long long base = (long long)(tt << 5) * 64;
            const long long o1 = base + lane * 32;
            const long long o2 = base + (32 + lane) * 32;
            prefetch_l2(x + ((o1 < nfloats) ? o1 : (nfloats - 32)));
            prefetch_l2(x + ((o2 < nfloats) ? o2 : (nfloats - 32)));
        }
    };

    float cnt[BINS], csum[BINS];
    #pragma unroll
    for (int b = 0; b < BINS; b++) { cnt[b] = 0.0f; csum[b] = 0.0f; }

    // --- prologue: stage tiles t, t+nw into buffers 0,1; prefetch t+2nw ---
    int t = gw;
    #pragma unroll
    for (int s = 0; s < 2; s++) {
        const int tp = t + s * nw;
        if (tp < ntiles) {
            const int rb = tp << 5;
            #pragma unroll
            for (int j = 0; j < 16; j++) {
                const int lr = 2 * j + r2;               // local row
                const int rc = min(rb + 2 * j, nrows - 2);
                const unsigned off = (unsigned)((lr * 16 + (c4 ^ (lr & 7))) << 4);
                cp_async16(dstS[s] + off, srcb + (size_t)rc * 64);
            }
        }
        cp_commit();
    }
    l2_prefetch_tile(t + 2 * nw);
    // prefetch target for tile t
    int tc_cur = (((t << 5) + lane) < nrows) ? __ldg(target + (t << 5) + lane) : 0;

    int cur = 0;
    while (t < ntiles) {
        const int tn  = t + nw;
        const int tp2 = t + 2 * nw;

        // L2-prefetch 3 tiles ahead (arrives before t+2nw's restage next iter)
        l2_prefetch_tile(t + 3 * nw);

        cp_wait<1>();            // tile t ready; tile t+nw still in flight
        __syncwarp();

        // prefetch next tile's target
        const int nrw = (tn << 5) + lane;
        const int tc_next = (nrw < nrows) ? __ldg(target + nrw) : 0;

        // ---- compute tile t: thread `lane` owns row (t<<5)+lane ----
        const bool valid = ((t << 5) + lane) < nrows;
        const int  tc    = tc_cur;
        const int  sw    = lane & 7;

        const float4* bp = (const float4*)&tile[wi][cur][0] + lane * 16;
        float s0 = 0.f, s1 = 0.f, s2 = 0.f, s3 = 0.f;
        #pragma unroll
        for (int i = 0; i < 16; i++) {
            const float4 v = bp[i ^ sw];
            s0 += __expf(v.x); s1 += __expf(v.y);
            s2 += __expf(v.z); s3 += __expf(v.w);
        }
        const float s  = (s0 + s1) + (s2 + s3);
        const float xt = tile[wi][cur][lane * 64 + (((tc >> 2) ^ sw) << 2) + (tc & 3)];

        const float log_pt = xt - __logf(s);
        const float wt = stage1 ? 1.0f : __ldg(weight + tc);
        const float ce = -wt * log_pt;
        const float g  = fabsf(__expf(log_pt) - 1.0f);
        int b = (int)(g * 9.9999f);          // floor(g * (BINS - 1e-4)), g >= 0
        b = min(b, BINS - 1);

        if (valid) {
            #pragma unroll
            for (int k = 0; k < BINS; k++) {
                const bool h = (b == k);
                cnt[k]  += h ? 1.0f : 0.0f;
                csum[k] += h ? ce   : 0.0f;
            }
        }
        __syncwarp();

        // restage this buffer with tile t+2*nw (should be L2-resident now)
        if (tp2 < ntiles) {
            const int rb = tp2 << 5;
            const unsigned d = dstS[cur];
            #pragma unroll
            for (int j = 0; j < 16; j++) {
                const int lr = 2 * j + r2;
                const int rc = min(rb + 2 * j, nrows - 2);
                const unsigned off = (unsigned)((lr * 16 + (c4 ^ (lr & 7))) << 4);
                cp_async16(d + off, srcb + (size_t)rc * 64);
            }
        }
        cp_commit();

        tc_cur = tc_next;
        cur ^= 1;
        t = tn;
    }

    // fold 20 accumulators across the warp (once per kernel)
    #pragma unroll
    for (int k = 0; k < BINS; k++) {
        #pragma unroll
        for (int m = 16; m > 0; m >>= 1) {
            cnt[k]  += __shfl_xor_sync(0xffffffffu, cnt[k],  m);
            csum[k] += __shfl_xor_sync(0xffffffffu, csum[k], m);
        }
    }
    __syncthreads();                 // s_cnt/s_sum zero-init visible
    if (lane == 0) {
        #pragma unroll
        for (int k = 0; k < BINS; k++) {
            atomicAdd(&s_cnt[k], cnt[k]);
            atomicAdd(&s_sum[k], csum[k]);
        }
    }
    __syncthreads();
    if (tid < BINS) {
        atomicAdd(&g_cnt[tid], s_cnt[tid]);
        atomicAdd(&g_sum[tid], s_sum[tid]);
    }
    __threadfence();
    __syncthreads();
    if (tid == 0) {
        const unsigned prev = atomicAdd(&g_done, 1u);
        s_last = (prev == gridDim.x - 1);
    }
    __syncthreads();

    if (s_last && tid == 0) {
        float c[BINS], su[BINS];
        #pragma unroll
        for (int b = 0; b < BINS; b++) { c[b] = g_cnt[b]; su[b] = g_sum[b]; }
        float nonempty = 0.0f;
        #pragma unroll
        for (int b = 0; b < BINS; b++)
            nonempty += (c[b] > 0.0f) ? 1.0f : 0.0f;
        float loss = 0.0f;
        #pragma unroll
        for (int b = 0; b < BINS; b++)
            loss += su[b] / fmaxf(c[b] * nonempty, 0.0001f);
        out[0] = loss * invN;
        // self-clean for next graph replay
        #pragma unroll
        for (int b = 0; b < BINS; b++) { g_cnt[b] = 0.0f; g_sum[b] = 0.0f; }
        g_done = 0;
        __threadfence();
    }
}

extern "C" void kernel_launch(void* const* d_in, const int* in_sizes, int n_in,
                              void* d_out, int out_size) {
    const float* x      = (const float*)d_in[0];
    const int*   target = (const int*)  d_in[1];
    const float* weight = (const float*)d_in[2];
    const int*   stage  = (const int*)  d_in[3];
    float*       out    = (float*)      d_out;

    const int N = in_sizes[1];   // number of samples

    ghm_fused<<<GRID_BLKS, NTHR>>>(x, target, weight, stage,
                                   out, N, 1.0f / (float)N);
}

// round 12
// speedup vs baseline: 1.0747x; 1.0354x over previous
#include <cuda_runtime.h>
#include <cuda_bf16.h>
#include <cstdint>

#define BINS  10
#define WPB   7                 // warps per block
#define NTHR  224
#define GRID_BLKS 296           // 148 SMs * 2 blocks (smem-limited)
// Per warp: two 8 KB buffers (32 rows x 64 f32). A 32-row tile is 8 KB
// CONTIGUOUS in gmem -> ONE cp.async.bulk (TMA bulk engine) per tile,
// mbarrier completion. No swizzle needed: compute reads chunks in rotated
// order (i+lane)&15 -> bank-group (lane+i)%8, conflict-free LDS.128.

__device__ float    g_cnt[BINS];
__device__ float    g_sum[BINS];
__device__ unsigned g_done = 0;   // last block resets everything (graph-replay safe)

__device__ __forceinline__ void mbar_init(unsigned a, unsigned cnt) {
    asm volatile("mbarrier.init.shared.b64 [%0], %1;" :: "r"(a), "r"(cnt) : "memory");
}
__device__ __forceinline__ void mbar_expect_tx(unsigned a, unsigned bytes) {
    asm volatile("mbarrier.arrive.expect_tx.shared.b64 _, [%0], %1;"
                 :: "r"(a), "r"(bytes) : "memory");
}
__device__ __forceinline__ void bulk_g2s(unsigned dst, const void* src,
                                         unsigned bytes, unsigned mbar) {
    asm volatile(
        "cp.async.bulk.shared::cluster.global.mbarrier::complete_tx::bytes "
        "[%0], [%1], %2, [%3];"
        :: "r"(dst), "l"(src), "r"(bytes), "r"(mbar) : "memory");
}
__device__ __forceinline__ void mbar_wait(unsigned a, unsigned parity) {
    asm volatile(
        "{\n\t"
        ".reg .pred P;\n\t"
        "WL_%=:\n\t"
        "mbarrier.try_wait.parity.acquire.cta.shared::cta.b64 P, [%0], %1, 0x989680;\n\t"
        "@P bra.uni WD_%=;\n\t"
        "bra.uni WL_%=;\n\t"
        "WD_%=:\n\t"
        "}"
        :: "r"(a), "r"(parity) : "memory");
}
__device__ __forceinline__ void fence_async_shared() {
    asm volatile("fence.proxy.async.shared::cta;" ::: "memory");
}

__global__ __launch_bounds__(NTHR, 2)
void ghm_fused(const float* __restrict__ x,
               const int*   __restrict__ target,
               const float* __restrict__ weight,
               const int*   __restrict__ stage,
               float*       __restrict__ out,
               int nrows, float invN)
{
    __shared__ __align__(16) float tile[WPB][2][32 * 64];   // 8 KB per buffer
    __shared__ __align__(8)  unsigned long long mbar[WPB][2];
    __shared__ float s_cnt[BINS];
    __shared__ float s_sum[BINS];
    __shared__ bool  s_last;

    const int tid  = threadIdx.x;
    const int wi   = tid >> 5;
    const int lane = tid & 31;

    if (tid < BINS) { s_cnt[tid] = 0.0f; s_sum[tid] = 0.0f; }

    const int sraw = __ldg(stage);
    const bool stage1 = (sraw == 1) || (__int_as_float(sraw) == 1.0f);

    const int gw     = blockIdx.x * WPB + wi;   // global warp id
    const int nw     = gridDim.x * WPB;         // total warps
    const int ntiles = (nrows + 31) >> 5;

    unsigned bufA[2], mbA[2];
    #pragma unroll
    for (int s = 0; s < 2; s++) {
        bufA[s] = (unsigned)__cvta_generic_to_shared(&tile[wi][s][0]);
        mbA[s]  = (unsigned)__cvta_generic_to_shared(&mbar[wi][s]);
    }

    // per-warp mbarrier init (producer == consumer warp)
    if (lane == 0) { mbar_init(mbA[0], 1); mbar_init(mbA[1], 1); }
    fence_async_shared();
    __syncwarp();

    // elected-lane bulk issue of tile tt into buffer s
    auto issue_tile = [&](int tt, int s) {
        if (tt < ntiles && lane == 0) {
            const int rb   = tt << 5;
            const int rows = min(32, nrows - rb);
            const unsigned bytes = (unsigned)rows * 256u;
            mbar_expect_tx(mbA[s], bytes);
            bulk_g2s(bufA[s], x + (size_t)rb * 64, bytes, mbA[s]);
        }
    };

    float cnt[BINS], csum[BINS];
    #pragma unroll
    for (int b = 0; b < BINS; b++) { cnt[b] = 0.0f; csum[b] = 0.0f; }

    // prologue: tiles t, t+nw in flight
    int t = gw;
    issue_tile(t, 0);
    issue_tile(t + nw, 1);
    int tc_cur = (((t << 5) + lane) < nrows) ? __ldg(target + (t << 5) + lane) : 0;

    int ph0 = 0, ph1 = 0;
    int cur = 0;
    while (t < ntiles) {
        const int tn = t + nw;

        mbar_wait(mbA[cur], cur ? ph1 : ph0);

        // prefetch next tile's target
        const int nrw = (tn << 5) + lane;
        const int tc_next = (nrw < nrows) ? __ldg(target + nrw) : 0;

        // ---- compute tile t: thread `lane` owns row (t<<5)+lane ----
        const bool valid = ((t << 5) + lane) < nrows;
        const int  tc    = tc_cur;

        const float4* bp = (const float4*)&tile[wi][cur][0] + lane * 16;
        float s0 = 0.f, s1 = 0.f, s2 = 0.f, s3 = 0.f;
        #pragma unroll
        for (int i = 0; i < 16; i++) {
            const float4 v = bp[(i + lane) & 15];   // rotated: conflict-free
            s0 += __expf(v.x); s1 += __expf(v.y);
            s2 += __expf(v.z); s3 += __expf(v.w);
        }
        const float s  = (s0 + s1) + (s2 + s3);
        const float xt = tile[wi][cur][lane * 64 + tc];

        const float log_pt = xt - __logf(s);
        const float wt = stage1 ? 1.0f : __ldg(weight + tc);
        const float ce = -wt * log_pt;
        const float g  = fabsf(__expf(log_pt) - 1.0f);
        int b = (int)(g * 9.9999f);          // floor(g * (BINS - 1e-4)), g >= 0
        b = min(b, BINS - 1);

        if (valid) {
            #pragma unroll
            for (int k = 0; k < BINS; k++) {
                const bool h = (b == k);
                cnt[k]  += h ? 1.0f : 0.0f;
                csum[k] += h ? ce   : 0.0f;
            }
        }
        __syncwarp();            // all lanes done reading this buffer
        fence_async_shared();    // order generic reads before async-proxy write

        // restage this buffer with tile t+2*nw
        issue_tile(t + 2 * nw, cur);
        if (cur) ph1 ^= 1; else ph0 ^= 1;

        tc_cur = tc_next;
        cur ^= 1;
        t = tn;
    }

    // fold 20 accumulators across the warp (once per kernel)
    #pragma unroll
    for (int k = 0; k < BINS; k++) {
        #pragma unroll
        for (int m = 16; m > 0; m >>= 1) {
            cnt[k]  += __shfl_xor_sync(0xffffffffu, cnt[k],  m);
            csum[k] += __shfl_xor_sync(0xffffffffu, csum[k], m);
        }
    }
    __syncthreads();                 // s_cnt/s_sum zero-init visible
    if (lane == 0) {
        #pragma unroll
        for (int k = 0; k < BINS; k++) {
            atomicAdd(&s_cnt[k], cnt[k]);
            atomicAdd(&s_sum[k], csum[k]);
        }
    }
    __syncthreads();
    if (tid < BINS) {
        atomicAdd(&g_cnt[tid], s_cnt[tid]);
        atomicAdd(&g_sum[tid], s_sum[tid]);
    }
    __threadfence();
    __syncthreads();
    if (tid == 0) {
        const unsigned prev = atomicAdd(&g_done, 1u);
        s_last = (prev == gridDim.x - 1);
    }
    __syncthreads();

    if (s_last && tid == 0) {
        float c[BINS], su[BINS];
        #pragma unroll
        for (int b = 0; b < BINS; b++) { c[b] = g_cnt[b]; su[b] = g_sum[b]; }
        float nonempty = 0.0f;
        #pragma unroll
        for (int b = 0; b < BINS; b++)
            nonempty += (c[b] > 0.0f) ? 1.0f : 0.0f;
        float loss = 0.0f;
        #pragma unroll
        for (int b = 0; b < BINS; b++)
            loss += su[b] / fmaxf(c[b] * nonempty, 0.0001f);
        out[0] = loss * invN;
        // self-clean for next graph replay
        #pragma unroll
        for (int b = 0; b < BINS; b++) { g_cnt[b] = 0.0f; g_sum[b] = 0.0f; }
        g_done = 0;
        __threadfence();
    }
}

extern "C" void kernel_launch(void* const* d_in, const int* in_sizes, int n_in,
                              void* d_out, int out_size) {
    const float* x      = (const float*)d_in[0];
    const int*   target = (const int*)  d_in[1];
    const float* weight = (const float*)d_in[2];
    const int*   stage  = (const int*)  d_in[3];
    float*       out    = (float*)      d_out;

    const int N = in_sizes[1];   // number of samples

    ghm_fused<<<GRID_BLKS, NTHR>>>(x, target, weight, stage,
                                   out, N, 1.0f / (float)N);
}